// round 6
// baseline (speedup 1.0000x reference)
#include <cuda_runtime.h>
#include <cuda_bf16.h>
#include <math.h>

#define Bb 8
#define Nn 16384
#define Dd 768
#define Rr 3
#define NE 4
#define NBLK 16384         // proj/out blocks: (B*N)/8 = 131072/8
#define BLK_PER_B 2048     // NBLK / Bb

// Scratch (allocation-free rule: __device__ globals)
__device__ float g_xr[Bb * Rr * Nn];     // (B,R,N): NCHW image (b,r,h,w)
__device__ float g_part[NBLK * Rr];      // per-proj-block partial sums of xr
__device__ float g_G[Bb * NE];
__device__ float g_c64[Bb * Rr * 64 * 64];
__device__ float g_c32[Bb * Rr * 32 * 32];
__device__ float g_c16[Bb * Rr * 16 * 16];

// ---------------------------------------------------------------------------
// Kernel 1: xr = x @ Wd + bd  (+ per-block partial sums for the mean).
// Warp per row, Wd in smem, float4 loads. grid = 16384 x 256.
// ---------------------------------------------------------------------------
__global__ void k_proj(const float* __restrict__ x,
                       const float* __restrict__ Wd,
                       const float* __restrict__ bd) {
    __shared__ float sWd[Dd * Rr];
    __shared__ float sp[8][3];
    int tid = threadIdx.x;
    for (int i = tid; i < Dd * Rr; i += blockDim.x) sWd[i] = Wd[i];
    __syncthreads();

    int warp = tid >> 5, lane = tid & 31;
    int row = blockIdx.x * 8 + warp;              // [0, B*N)
    const float4* xr4 = (const float4*)(x + (long long)row * Dd);

    float a0 = 0.f, a1 = 0.f, a2 = 0.f;
#pragma unroll
    for (int k = 0; k < 6; k++) {
        int f4i = lane + 32 * k;                  // 192 float4 per row
        float4 v = xr4[f4i];
        int d0 = f4i * 4;
        const float* w = &sWd[d0 * 3];
        a0 += v.x * w[0] + v.y * w[3] + v.z * w[6] + v.w * w[9];
        a1 += v.x * w[1] + v.y * w[4] + v.z * w[7] + v.w * w[10];
        a2 += v.x * w[2] + v.y * w[5] + v.z * w[8] + v.w * w[11];
    }
#pragma unroll
    for (int off = 16; off > 0; off >>= 1) {
        a0 += __shfl_down_sync(0xffffffffu, a0, off);
        a1 += __shfl_down_sync(0xffffffffu, a1, off);
        a2 += __shfl_down_sync(0xffffffffu, a2, off);
    }
    if (lane == 0) {
        int b = row >> 14, n = row & (Nn - 1);
        float s0 = a0 + bd[0], s1 = a1 + bd[1], s2 = a2 + bd[2];
        g_xr[((long long)b * Rr + 0) * Nn + n] = s0;
        g_xr[((long long)b * Rr + 1) * Nn + n] = s1;
        g_xr[((long long)b * Rr + 2) * Nn + n] = s2;
        sp[warp][0] = s0; sp[warp][1] = s1; sp[warp][2] = s2;
    }
    __syncthreads();
    if (tid == 0) {
        float p0 = 0.f, p1 = 0.f, p2 = 0.f;
#pragma unroll
        for (int w = 0; w < 8; w++) { p0 += sp[w][0]; p1 += sp[w][1]; p2 += sp[w][2]; }
        g_part[blockIdx.x * 3 + 0] = p0;
        g_part[blockIdx.x * 3 + 1] = p1;
        g_part[blockIdx.x * 3 + 2] = p2;
    }
}

// ---------------------------------------------------------------------------
// Kernel 2: blocks 0..23 = small-scale pyramid; block 24 = mean-reduce + gate.
// ---------------------------------------------------------------------------
__device__ __forceinline__ void conv3x3_g(const float* __restrict__ in,
                                          float* __restrict__ out, int S,
                                          const float* k9, float kb,
                                          int t, int nt) {
    for (int i = t; i < S * S; i += nt) {
        int y = i / S, x = i - y * S;
        float v = kb;
#pragma unroll
        for (int ky = 0; ky < 3; ky++) {
            int yy = y + ky - 1;
            if (yy < 0 || yy >= S) continue;
#pragma unroll
            for (int kx = 0; kx < 3; kx++) {
                int xx = x + kx - 1;
                if (xx < 0 || xx >= S) continue;
                v += in[yy * S + xx] * k9[ky * 3 + kx];
            }
        }
        out[i] = v;
    }
}

__global__ void k_mid(const float* __restrict__ dwk,
                      const float* __restrict__ dwb,
                      const float* __restrict__ noise,
                      const float* __restrict__ Wg,
                      const float* __restrict__ Wn) {
    int t = threadIdx.x;
    if (blockIdx.x == 24) {
        // ---- mean reduce (two-stage, fixed deterministic schedule) + gate ----
        __shared__ float red[24][8];
        __shared__ float xa[Bb * Rr];
        int gidx = t >> 3, sub = t & 7;
        if (gidx < 24) {
            int b = gidx / Rr, r = gidx - (gidx / Rr) * Rr;
            // batch b owns proj blocks [b*2048, (b+1)*2048); sub covers a
            // contiguous 256-block slice in fixed serial order.
            const float* p = g_part + (b * BLK_PER_B + sub * 256) * 3 + r;
            float s = 0.f;
#pragma unroll 8
            for (int i = 0; i < 256; i++) s += p[i * 3];
            red[gidx][sub] = s;
        }
        __syncthreads();
        if (t < 24) {
            float s = 0.f;
#pragma unroll
            for (int k = 0; k < 8; k++) s += red[t][k];
            xa[t] = s * (1.0f / (float)Nn);
        }
        __syncthreads();
        if (t < Bb) {
            int b = t;
            float xa0 = xa[b * 3 + 0], xa1 = xa[b * 3 + 1], xa2 = xa[b * 3 + 2];
            float hl[NE];
#pragma unroll
            for (int e = 0; e < NE; e++) {
                float hg = xa0 * Wg[0 * NE + e] + xa1 * Wg[1 * NE + e] + xa2 * Wg[2 * NE + e];
                float hn = xa0 * Wn[0 * NE + e] + xa1 * Wn[1 * NE + e] + xa2 * Wn[2 * NE + e];
                float sp = (hn > 0.f) ? hn + log1pf(expf(-hn)) : log1pf(expf(hn));
                hl[e] = hg + noise[b * NE + e] * sp;
            }
            int i1 = 0;
#pragma unroll
            for (int e = 1; e < NE; e++) if (hl[e] > hl[i1]) i1 = e;
            int i2 = -1;
#pragma unroll
            for (int e = 0; e < NE; e++) {
                if (e == i1) continue;
                if (i2 < 0 || hl[e] > hl[i2]) i2 = e;
            }
            float e2 = expf(hl[i2] - hl[i1]);
            float inv = 1.0f / (1.0f + e2);
            float g[NE] = {0.f, 0.f, 0.f, 0.f};
            g[i1] = inv;
            g[i2] = e2 * inv;
#pragma unroll
            for (int e = 0; e < NE; e++) g_G[b * NE + e] = g[e];
        }
        return;
    }

    // ---- pyramid: one block per (b,r) ----
    __shared__ float d64[64 * 64];
    __shared__ float d32[32 * 32];
    __shared__ float d16[16 * 16];

    int br = blockIdx.x;
    int r = br % Rr;
    const float* img = g_xr + (long long)br * Nn;   // 128x128

    float k9[9];
#pragma unroll
    for (int i = 0; i < 9; i++) k9[i] = dwk[r * 9 + i];
    float kb = dwb[r];

    for (int i = t; i < 64 * 64; i += 256) {
        int y = i >> 6, x = i & 63;
        const float* p0 = img + (2 * y) * 128 + 2 * x;
        d64[i] = 0.25f * (p0[0] + p0[1] + p0[128] + p0[129]);
    }
    for (int i = t; i < 32 * 32; i += 256) {
        int y = i >> 5, x = i & 31;
        const float* p0 = img + (4 * y + 1) * 128 + 4 * x + 1;
        d32[i] = 0.25f * (p0[0] + p0[1] + p0[128] + p0[129]);
    }
    for (int i = t; i < 16 * 16; i += 256) {
        int y = i >> 4, x = i & 15;
        const float* p0 = img + (8 * y + 3) * 128 + 8 * x + 3;
        d16[i] = 0.25f * (p0[0] + p0[1] + p0[128] + p0[129]);
    }
    __syncthreads();
    conv3x3_g(d64, g_c64 + br * 64 * 64, 64, k9, kb, t, 256);
    conv3x3_g(d32, g_c32 + br * 32 * 32, 32, k9, kb, t, 256);
    conv3x3_g(d16, g_c16 + br * 16 * 16, 16, k9, kb, t, 256);
}

// ---------------------------------------------------------------------------
// Kernel 3: fused mix + epilogue.  192 threads, 8 consecutive pixels/block.
// Threads 0..23 compute mixed (3 r x 8 px) from L2-hot scratch; then all
// threads do out = x + mixed @ Wu + bu with Wu/bu in registers.
// ---------------------------------------------------------------------------
__device__ __forceinline__ float up_bilin_g(const float* __restrict__ c, int S,
                                            int y, int x, float a, float off) {
    float py = a * (float)y + off;
    float px = a * (float)x + off;
    float fy = floorf(py), fx = floorf(px);
    float wy = py - fy, wx = px - fx;
    int y0 = (int)fy, x0 = (int)fx;
    int y1 = y0 + 1, x1 = x0 + 1;
    y0 = max(0, min(S - 1, y0)); y1 = max(0, min(S - 1, y1));
    x0 = max(0, min(S - 1, x0)); x1 = max(0, min(S - 1, x1));
    float v00 = __ldg(c + y0 * S + x0), v01 = __ldg(c + y0 * S + x1);
    float v10 = __ldg(c + y1 * S + x0), v11 = __ldg(c + y1 * S + x1);
    float v0 = v00 + wx * (v01 - v00);
    float v1 = v10 + wx * (v11 - v10);
    return v0 + wy * (v1 - v0);
}

__global__ void k_out(const float* __restrict__ x,
                      const float* __restrict__ Wu,
                      const float* __restrict__ bu,
                      const float* __restrict__ dwk,
                      const float* __restrict__ dwb,
                      float* __restrict__ out) {
    __shared__ float sm[Rr][8];
    int t = threadIdx.x;  // 0..191
    long long row0 = (long long)blockIdx.x * 8;
    int b = (int)(row0 >> 14);
    int n0 = (int)(row0 & (Nn - 1));
    int yy = n0 >> 7, xx0 = n0 & 127;             // 8 px share row yy

    // ---- phase 1: mixed for this block's 8 pixels (threads 0..23) ----
    if (t < 24) {
        int r = t >> 3, p = t & 7;
        int xx = xx0 + p;
        int br = b * Rr + r;
        const float* img = g_xr + (long long)br * Nn;
        float v = __ldg(dwb + r);
#pragma unroll
        for (int ky = 0; ky < 3; ky++) {
            int ry = yy + ky - 1;
            if (ry < 0 || ry >= 128) continue;
#pragma unroll
            for (int kx = 0; kx < 3; kx++) {
                int rx = xx + kx - 1;
                if (rx < 0 || rx >= 128) continue;
                v += __ldg(img + ry * 128 + rx) * __ldg(dwk + r * 9 + ky * 3 + kx);
            }
        }
        float u1 = up_bilin_g(g_c64 + br * 64 * 64, 64, yy, xx, 0.5f,   -0.25f);
        float u2 = up_bilin_g(g_c32 + br * 32 * 32, 32, yy, xx, 0.25f,  -0.375f);
        float u3 = up_bilin_g(g_c16 + br * 16 * 16, 16, yy, xx, 0.125f, -0.4375f);
        float G0 = g_G[b * NE + 0], G1 = g_G[b * NE + 1];
        float G2 = g_G[b * NE + 2], G3 = g_G[b * NE + 3];
        sm[r][p] = G0 * v + G1 * u1 + G2 * u2 + G3 * u3;
    }

    // weight loads overlap phase 1
    const float4* Wu4 = (const float4*)Wu;
    float4 w0 = Wu4[t], w1 = Wu4[192 + t], w2 = Wu4[384 + t];
    float4 bv = ((const float4*)bu)[t];
    __syncthreads();

    // ---- phase 2: epilogue ----
#pragma unroll
    for (int i = 0; i < 8; i++) {
        long long row = row0 + i;
        float m0 = sm[0][i], m1 = sm[1][i], m2 = sm[2][i];
        float4 xv = ((const float4*)(x + row * Dd))[t];
        float4 rv;
        rv.x = xv.x + m0 * w0.x + m1 * w1.x + m2 * w2.x + bv.x;
        rv.y = xv.y + m0 * w0.y + m1 * w1.y + m2 * w2.y + bv.y;
        rv.z = xv.z + m0 * w0.z + m1 * w1.z + m2 * w2.z + bv.z;
        rv.w = xv.w + m0 * w0.w + m1 * w1.w + m2 * w2.w + bv.w;
        ((float4*)out)[row * 192 + t] = rv;
    }
}

// ---------------------------------------------------------------------------
extern "C" void kernel_launch(void* const* d_in, const int* in_sizes, int n_in,
                              void* d_out, int out_size) {
    const float* x     = (const float*)d_in[0];
    const float* noise = (const float*)d_in[1];
    const float* Wd    = (const float*)d_in[2];
    const float* bd    = (const float*)d_in[3];
    const float* Wu    = (const float*)d_in[4];
    const float* bu    = (const float*)d_in[5];
    const float* Wg    = (const float*)d_in[6];
    const float* Wn    = (const float*)d_in[7];
    const float* dwk   = (const float*)d_in[8];
    const float* dwb   = (const float*)d_in[9];
    float* out = (float*)d_out;

    k_proj<<<NBLK, 256>>>(x, Wd, bd);
    k_mid<<<25, 256>>>(dwk, dwb, noise, Wg, Wn);
    k_out<<<NBLK, 192>>>(x, Wu, bu, dwk, dwb, out);
}